// round 11
// baseline (speedup 1.0000x reference)
#include <cuda_runtime.h>
#include <cuda_fp16.h>
#include <cstdint>

// Problem constants
#define BB   4
#define HH   56
#define WW   56
#define CC   256
#define NH   8
#define HD   32
#define NN   (HH*WW)          // 3136
#define SS   (NN + 1)         // 3137
#define SP   3328             // padded seq stride (13*256, 52*64)
#define MROWS (BB * SS)       // 12548
#define BHN  (BB * NH)        // 32

// Scratch (device globals; zero-initialized — padding stays 0)
__device__ float g_attn[(size_t)BB * SS * CC];
__device__ __half g_q[(size_t)BHN * SP * HD];    // pre-scaled by 1/sqrt(hd)*log2(e)
__device__ __half g_k[(size_t)BHN * SP * HD];
__device__ __half g_vt[(size_t)BHN * HD * SP];   // V^T: [bh][d][s]
__device__ float  g_vsum[BB * CC];               // fp32 exact sum_s V[s][d] (b,h,d)
__device__ float  g_xpart[256][CC];              // partial column sums of x

// ---------------------------------------------------------------------------
// PTX helpers (baseline-PTX instructions only)
// ---------------------------------------------------------------------------
__device__ __forceinline__ uint32_t smem_u32(const void* p) {
    uint32_t a;
    asm("{ .reg .u64 t; cvta.to.shared.u64 t, %1; cvt.u32.u64 %0, t; }"
        : "=r"(a) : "l"(p));
    return a;
}
__device__ __forceinline__ void mma16816h(float* d, const uint32_t* a,
                                          const uint32_t* b, const float* c) {
    asm volatile(
        "mma.sync.aligned.m16n8k16.row.col.f32.f16.f16.f32 "
        "{%0,%1,%2,%3}, {%4,%5,%6,%7}, {%8,%9}, {%10,%11,%12,%13};"
        : "=f"(d[0]), "=f"(d[1]), "=f"(d[2]), "=f"(d[3])
        : "r"(a[0]), "r"(a[1]), "r"(a[2]), "r"(a[3]),
          "r"(b[0]), "r"(b[1]),
          "f"(c[0]), "f"(c[1]), "f"(c[2]), "f"(c[3]));
}
__device__ __forceinline__ void ldm4(uint32_t* r, uint32_t a) {
    asm volatile("ldmatrix.sync.aligned.m8n8.x4.shared.b16 {%0,%1,%2,%3}, [%4];"
                 : "=r"(r[0]), "=r"(r[1]), "=r"(r[2]), "=r"(r[3]) : "r"(a));
}
__device__ __forceinline__ float ex2(float x) {
    float r;
    asm("ex2.approx.ftz.f32 %0, %1;" : "=f"(r) : "f"(x));
    return r;
}
// pack two f32 -> f16x2 (lo half = first arg)
__device__ __forceinline__ uint32_t packh(float lo, float hi) {
    uint32_t r;
    asm("cvt.rn.f16x2.f32 %0, %1, %2;" : "=r"(r) : "f"(hi), "f"(lo));
    return r;
}
__device__ __forceinline__ uint32_t ex2h2(uint32_t s) {
    uint32_t r;
    asm("ex2.approx.f16x2 %0, %1;" : "=r"(r) : "r"(s));
    return r;
}
__device__ __forceinline__ uint32_t hsub2u(uint32_t a, uint32_t b) {
    uint32_t r;
    asm("sub.rn.f16x2 %0, %1, %2;" : "=r"(r) : "r"(a), "r"(b));
    return r;
}
__device__ __forceinline__ uint32_t hadd2u(uint32_t a, uint32_t b) {
    uint32_t r;
    asm("add.rn.f16x2 %0, %1, %2;" : "=r"(r) : "r"(a), "r"(b));
    return r;
}
#define CP16(dst, src) asm volatile("cp.async.cg.shared.global [%0], [%1], 16;" :: "r"(dst), "l"(src) : "memory")
#define CPCOMMIT()     asm volatile("cp.async.commit_group;" ::: "memory")
#define CPWAIT1()      asm volatile("cp.async.wait_group 1;" ::: "memory")

// ---------------------------------------------------------------------------
// fp16 tensor-core GEMM: C[M,N] = A[M,256] * W[N,256]^T (+bias)
// Block tile 128x128, 8 warps of 32x64. K staged 32/iter, fp32->fp16 in regs.
// mode 0: A = concat(cls, x); outputs fp16 Q (pre-scaled), K, V^T
// mode 1: A = g_attn; outputs -> d_out (x part / cls part) with bias
// ---------------------------------------------------------------------------
#define STA 40    // smem row stride in halves (80B) — ldmatrix conflict-free
__global__ __launch_bounds__(256, 2) void hgemm_kernel(
    const float* __restrict__ x, const float* __restrict__ cls,
    const float* __restrict__ w, const float* __restrict__ bias,
    float* __restrict__ out_x, float* __restrict__ out_cls, int mode)
{
    __shared__ alignas(16) uint16_t As[128 * STA];
    __shared__ alignas(16) uint16_t Bs[128 * STA];

    const int t    = threadIdx.x;
    const int wp   = t >> 5, lane = t & 31;
    const int wy   = wp >> 1, wx = wp & 1;
    const int g    = lane >> 2, m2 = (lane & 3) * 2;
    const int row0 = blockIdx.x * 128;
    const int col0 = blockIdx.y * 128;

    // staging: thread t handles row t>>1, 16-col half (t&1)
    const int sr = t >> 1;
    const int sc = (t & 1) * 16;

    const float* asrc = nullptr;
    {
        int arow = row0 + sr;
        if (arow < MROWS) {
            if (mode == 0) {
                int ab = arow / SS, asq = arow - ab * SS;
                asrc = (asq == 0) ? (cls + (size_t)ab * CC)
                                  : (x + ((size_t)ab * NN + (asq - 1)) * CC);
            } else {
                asrc = g_attn + (size_t)arow * CC;
            }
        }
    }
    const float* bsrc = w + (size_t)(col0 + sr) * CC + sc;

    // ldmatrix base addresses
    const uint32_t aaddr0 = smem_u32(As)
        + (uint32_t)(wy * 32 + (lane & 15)) * (STA * 2) + (lane >> 4) * 16;
    const uint32_t baddr0 = smem_u32(Bs)
        + (uint32_t)(wx * 64 + (lane & 7)) * (STA * 2) + (lane >> 3) * 16;

    float acc[2][8][4];
#pragma unroll
    for (int f = 0; f < 2; f++)
#pragma unroll
        for (int j = 0; j < 8; j++)
#pragma unroll
            for (int c = 0; c < 4; c++) acc[f][j][c] = 0.f;

    float4 abuf[4], bbuf[4];
    // prologue: load stage 0
#pragma unroll
    for (int q = 0; q < 4; q++) {
        abuf[q] = asrc ? *(const float4*)(asrc + sc + q * 4)
                       : make_float4(0.f, 0.f, 0.f, 0.f);
        bbuf[q] = *(const float4*)(bsrc + q * 4);
    }

    uint16_t* ap = As + sr * STA + sc;
    uint16_t* bp = Bs + sr * STA + sc;

    for (int st = 0; st < 8; st++) {
        // convert + store current stage
        {
            uint4 u0 = make_uint4(packh(abuf[0].x, abuf[0].y), packh(abuf[0].z, abuf[0].w),
                                  packh(abuf[1].x, abuf[1].y), packh(abuf[1].z, abuf[1].w));
            uint4 u1 = make_uint4(packh(abuf[2].x, abuf[2].y), packh(abuf[2].z, abuf[2].w),
                                  packh(abuf[3].x, abuf[3].y), packh(abuf[3].z, abuf[3].w));
            *(uint4*)ap = u0; *(uint4*)(ap + 8) = u1;
            uint4 v0 = make_uint4(packh(bbuf[0].x, bbuf[0].y), packh(bbuf[0].z, bbuf[0].w),
                                  packh(bbuf[1].x, bbuf[1].y), packh(bbuf[1].z, bbuf[1].w));
            uint4 v1 = make_uint4(packh(bbuf[2].x, bbuf[2].y), packh(bbuf[2].z, bbuf[2].w),
                                  packh(bbuf[3].x, bbuf[3].y), packh(bbuf[3].z, bbuf[3].w));
            *(uint4*)bp = v0; *(uint4*)(bp + 8) = v1;
        }
        __syncthreads();

        // prefetch next stage (overlaps MMA)
        if (st < 7) {
            int off = (st + 1) * 32 + sc;
#pragma unroll
            for (int q = 0; q < 4; q++) {
                abuf[q] = asrc ? *(const float4*)(asrc + off + q * 4)
                               : make_float4(0.f, 0.f, 0.f, 0.f);
                bbuf[q] = *(const float4*)(bsrc + (st + 1) * 32 + q * 4);
            }
        }

        // MMA: 2 M-frags x 2 k-chunks x 8 n-chunks
        uint32_t af[2][2][4];
#pragma unroll
        for (int f = 0; f < 2; f++)
#pragma unroll
            for (int c = 0; c < 2; c++)
                ldm4(af[f][c], aaddr0 + f * (16 * STA * 2) + c * 32);
#pragma unroll
        for (int jn = 0; jn < 8; jn++) {
            uint32_t bf[4];
            ldm4(bf, baddr0 + jn * (8 * STA * 2));
            mma16816h(acc[0][jn], af[0][0], bf + 0, acc[0][jn]);
            mma16816h(acc[0][jn], af[0][1], bf + 2, acc[0][jn]);
            mma16816h(acc[1][jn], af[1][0], bf + 0, acc[1][jn]);
            mma16816h(acc[1][jn], af[1][1], bf + 2, acc[1][jn]);
        }
        __syncthreads();
    }

    // epilogue
    const float QSCALE = 0.17677669529663687f * 1.4426950408889634f;
#pragma unroll
    for (int f = 0; f < 2; f++) {
#pragma unroll
        for (int half = 0; half < 2; half++) {
            int row = row0 + wy * 32 + f * 16 + g + half * 8;
            if (row >= MROWS) continue;
            int b = row / SS, s = row - b * SS;
#pragma unroll
            for (int jn = 0; jn < 8; jn++) {
                int n = col0 + wx * 64 + jn * 8 + m2;
                float v0 = acc[f][jn][half * 2 + 0];
                float v1 = acc[f][jn][half * 2 + 1];
                if (mode == 0) {
                    int c3 = n >> 8, rem = n & 255;
                    int h = rem >> 5, d = rem & 31;
                    int bh = b * NH + h;
                    if (c3 == 0) {
                        *(__half2*)&g_q[((size_t)bh * SP + s) * HD + d] =
                            __floats2half2_rn(v0 * QSCALE, v1 * QSCALE);
                    } else if (c3 == 1) {
                        *(__half2*)&g_k[((size_t)bh * SP + s) * HD + d] =
                            __floats2half2_rn(v0, v1);
                    } else {
                        g_vt[((size_t)bh * HD + d) * SP + s]     = __float2half(v0);
                        g_vt[((size_t)bh * HD + d + 1) * SP + s] = __float2half(v1);
                    }
                } else {
                    v0 += bias[n]; v1 += bias[n + 1];
                    if (s == 0)
                        *(float2*)&out_cls[(size_t)b * CC + n] = make_float2(v0, v1);
                    else
                        *(float2*)&out_x[((size_t)b * NN + (s - 1)) * CC + n] =
                            make_float2(v0, v1);
                }
            }
        }
    }
}

// ---------------------------------------------------------------------------
// V column sums, two-stage (wide):
//  a) 256 blocks: partial column sums of x (49 rows each)
//  b) 4 blocks: reduce partials + cls, multiply by Wv^T row -> g_vsum
// ---------------------------------------------------------------------------
__global__ __launch_bounds__(256) void vsum_a_kernel(const float* __restrict__ x)
{
    const int blk = blockIdx.x;          // b*64 + chunk
    const int b   = blk >> 6, ch = blk & 63;
    const int c   = threadIdx.x;
    const float* p = x + ((size_t)b * NN + ch * 49) * CC + c;
    float s = 0.f;
#pragma unroll 7
    for (int r = 0; r < 49; r++) s += p[(size_t)r * CC];
    g_xpart[blk][c] = s;
}

__global__ __launch_bounds__(256) void vsum_b_kernel(
    const float* __restrict__ cls, const float* __restrict__ qkv_w)
{
    __shared__ float xs[256];
    const int b = blockIdx.x;
    const int t = threadIdx.x;
    float s = cls[b * CC + t];
#pragma unroll
    for (int k = 0; k < 64; k++) s += g_xpart[b * 64 + k][t];
    xs[t] = s;
    __syncthreads();
    const float* wr = qkv_w + (size_t)(2 * CC + t) * CC;   // Wv row t
    float acc = 0.f;
#pragma unroll 8
    for (int cc = 0; cc < CC; cc++) acc += xs[cc] * wr[cc];
    g_vsum[b * CC + t] = acc;
}

// ---------------------------------------------------------------------------
// Flash attention, fp16 mma.sync, mean-subtracted PV.
// 512 threads (16 warps), QTILE=256 q rows (16/warp), key tiles of 64,
// cp.async double buffer with ONE 16B op per thread per tile
// (threads 0-255 stage K, 256-511 stage V) — halves the LDGSTS issue floor.
// Tiles with kt >= MASK_FROM contain padded keys and take the masked path.
// ---------------------------------------------------------------------------
#define TKEY 64
#define QTILE 256
#define STK 40
#define STV 72
#define KT_TILES (SP / TKEY)     // 52
#define MASK_FROM (SS / TKEY)    // 49

__global__ __launch_bounds__(512, 1) void attn_mma_kernel()
{
    __shared__ alignas(16) uint16_t Kbuf[2][64 * STK];
    __shared__ alignas(16) uint16_t Vbuf[2][32 * STV];

    const int t    = threadIdx.x;
    const int w    = t >> 5;
    const int lane = t & 31;
    const int g    = lane >> 2;
    const int m2   = (lane & 3) * 2;
    const int bh   = blockIdx.y;
    const int q0   = blockIdx.x * QTILE;
    const int qrow = q0 + w * 16;

    // cp.async: one 16B chunk per thread per tile
    uint32_t dst0, dst1;
    const __half* src0;
    size_t tstep;
    if (t < 256) {
        int kr = t >> 2, kc4 = t & 3;          // K: 64 rows x 4 x 16B
        dst0 = smem_u32(&Kbuf[0][kr * STK + kc4 * 8]);
        dst1 = smem_u32(&Kbuf[1][kr * STK + kc4 * 8]);
        src0 = g_k + (size_t)bh * SP * HD + (size_t)kr * HD + kc4 * 8;
        tstep = (size_t)TKEY * HD;
    } else {
        int u = t - 256;
        int vr = u >> 3, vc8 = u & 7;          // V: 32 rows x 8 x 16B
        dst0 = smem_u32(&Vbuf[0][vr * STV + vc8 * 8]);
        dst1 = smem_u32(&Vbuf[1][vr * STV + vc8 * 8]);
        src0 = g_vt + ((size_t)bh * HD + vr) * SP + vc8 * 8;
        tstep = TKEY;
    }

    // ldmatrix lane addresses
    uint32_t kmat[2], vmat[2];
    {
        uint32_t ko = ((lane & 7) * STK + (lane >> 3) * 8) * 2;
        uint32_t vo = ((lane & 7) * STV + (lane >> 3) * 8) * 2;
        kmat[0] = smem_u32(Kbuf[0]) + ko; kmat[1] = smem_u32(Kbuf[1]) + ko;
        vmat[0] = smem_u32(Vbuf[0]) + vo; vmat[1] = smem_u32(Vbuf[1]) + vo;
    }

    // Q fragments (rows beyond SS read zero padding; SP bound never exceeded)
    uint32_t qa[2][4];
    {
        const __half* qb = g_q + (size_t)bh * SP * HD;
        int r0 = qrow + g, r1 = qrow + g + 8;
#pragma unroll
        for (int kc = 0; kc < 2; kc++) {
            int d0 = kc * 16 + m2, d1 = d0 + 8;
            qa[kc][0] = *(const uint32_t*)(qb + (size_t)r0 * HD + d0);
            qa[kc][1] = *(const uint32_t*)(qb + (size_t)r1 * HD + d0);
            qa[kc][2] = *(const uint32_t*)(qb + (size_t)r0 * HD + d1);
            qa[kc][3] = *(const uint32_t*)(qb + (size_t)r1 * HD + d1);
        }
    }

    float o[4][4];
#pragma unroll
    for (int i = 0; i < 4; i++)
#pragma unroll
        for (int j = 0; j < 4; j++) o[i][j] = 0.f;
    float la = 0.f, lb = 0.f;
    const uint32_t ONE2 = 0x3C003C00u;

    // prologue: prefetch tile 0
    CP16(dst0, src0);
    CPCOMMIT();

    for (int kt = 0; kt < KT_TILES; kt++) {
        const int cur = kt & 1;
        __syncthreads();
        if (kt + 1 < KT_TILES) {
            CP16(cur ? dst0 : dst1, src0 + (size_t)(kt + 1) * tstep);
        }
        CPCOMMIT();
        CPWAIT1();
        __syncthreads();

        // ---- S = Q K^T : 8 n-chunks, 1 fp16 term, 2 k-chunks ----
        float sf[8][4];
#pragma unroll
        for (int jn = 0; jn < 8; jn++) {
            uint32_t kb4[4];
            ldm4(kb4, kmat[cur] + jn * (8 * STK * 2));
            sf[jn][0] = sf[jn][1] = sf[jn][2] = sf[jn][3] = 0.f;
            mma16816h(sf[jn], qa[0], kb4 + 0, sf[jn]);
            mma16816h(sf[jn], qa[1], kb4 + 2, sf[jn]);
        }

        // ---- p = exp2(s) (f16x2 MUFU); f = p-1; l via f16x2 tree ----
        uint32_t fh[8][2];
        if (kt < MASK_FROM) {
            uint32_t t01[8], t23[8];
#pragma unroll
            for (int jn = 0; jn < 8; jn++) {
                uint32_t p01 = ex2h2(packh(sf[jn][0], sf[jn][1]));
                uint32_t p23 = ex2h2(packh(sf[jn][2], sf[jn][3]));
                fh[jn][0] = hsub2u(p01, ONE2);
                fh[jn][1] = hsub2u(p23, ONE2);
                t01[jn] = p01; t23[jn] = p23;
            }
            uint32_t a0 = hadd2u(hadd2u(t01[0], t01[1]), hadd2u(t01[2], t01[3]));
            uint32_t a1 = hadd2u(hadd2u(t01[4], t01[5]), hadd2u(t01[6], t01[7]));
            uint32_t b0 = hadd2u(hadd2u(t23[0], t23[1]), hadd2u(t23[2], t23[3]));
            uint32_t b1 = hadd2u(hadd2u(t23[4], t23[5]), hadd2u(t23[6], t23[7]));
            a0 = hadd2u(a0, a1);
            b0 = hadd2u(b0, b1);
            __half2 ha = *(__half2*)&a0;
            __half2 hb = *(__half2*)&b0;
            la += __low2float(ha) + __high2float(ha);
            lb += __low2float(hb) + __high2float(hb);
        } else {
            // padded-key tiles: exact scalar path with column masking
            const int kb = kt * TKEY;
#pragma unroll
            for (int jn = 0; jn < 8; jn++) {
                int col0 = kb + jn * 8 + m2;
                bool c0v = col0 < SS, c1v = (col0 + 1) < SS;
                float p0 = c0v ? ex2(sf[jn][0]) : 0.f;
                float p1 = c1v ? ex2(sf[jn][1]) : 0.f;
                float p2 = c0v ? ex2(sf[jn][2]) : 0.f;
                float p3 = c1v ? ex2(sf[jn][3]) : 0.f;
                la += p0 + p1;
                lb += p2 + p3;
                fh[jn][0] = packh(c0v ? (p0 - 1.f) : 0.f, c1v ? (p1 - 1.f) : 0.f);
                fh[jn][1] = packh(c0v ? (p2 - 1.f) : 0.f, c1v ? (p3 - 1.f) : 0.f);
            }
        }

        // ---- O += F V : 4 dim-chunks x 4 k-chunks, 1 fp16 term ----
        uint32_t pa[4][4];
#pragma unroll
        for (int kc2 = 0; kc2 < 4; kc2++) {
            pa[kc2][0] = fh[2 * kc2][0];
            pa[kc2][1] = fh[2 * kc2][1];
            pa[kc2][2] = fh[2 * kc2 + 1][0];
            pa[kc2][3] = fh[2 * kc2 + 1][1];
        }
#pragma unroll
        for (int jn2 = 0; jn2 < 4; jn2++) {
            uint32_t vv[8];
            ldm4(vv,     vmat[cur] + jn2 * (8 * STV * 2));
            ldm4(vv + 4, vmat[cur] + jn2 * (8 * STV * 2) + 64);
#pragma unroll
            for (int kc2 = 0; kc2 < 4; kc2++)
                mma16816h(o[jn2], pa[kc2], vv + 2 * kc2, o[jn2]);
        }
    }

    // ---- reduce l over quad, add Vsum, normalize, store ----
    la += __shfl_xor_sync(0xffffffffu, la, 1);
    la += __shfl_xor_sync(0xffffffffu, la, 2);
    lb += __shfl_xor_sync(0xffffffffu, lb, 1);
    lb += __shfl_xor_sync(0xffffffffu, lb, 2);
    const float ia = 1.f / la, ib = 1.f / lb;

    const int b = bh >> 3;
    const int h = bh & 7;
    const int r0 = qrow + g, r1 = qrow + g + 8;
#pragma unroll
    for (int jn2 = 0; jn2 < 4; jn2++) {
        float2 vs = *(const float2*)&g_vsum[b * CC + h * HD + jn2 * 8 + m2];
        if (r0 < SS) {
            float* dst = g_attn + ((size_t)b * SS + r0) * CC + h * HD + jn2 * 8 + m2;
            *(float2*)dst = make_float2((o[jn2][0] + vs.x) * ia,
                                        (o[jn2][1] + vs.y) * ia);
        }
        if (r1 < SS) {
            float* dst = g_attn + ((size_t)b * SS + r1) * CC + h * HD + jn2 * 8 + m2;
            *(float2*)dst = make_float2((o[jn2][2] + vs.x) * ib,
                                        (o[jn2][3] + vs.y) * ib);
        }
    }
}

// ---------------------------------------------------------------------------
// LePE: 5x5 depthwise conv (SAME), sliding-window version (unchanged)
// ---------------------------------------------------------------------------
#define XG 14
__global__ __launch_bounds__(256) void lepe_kernel(
    const float* __restrict__ x, const float* __restrict__ lw,
    const float* __restrict__ lb)
{
    __shared__ float wsh[25][256];
    const int c  = threadIdx.x;
    const int x0 = blockIdx.x * XG;
    const int y  = blockIdx.y;
    const int b  = blockIdx.z;

    for (int i = c; i < 25 * 256; i += 256)
        wsh[i % 25][i / 25] = lw[i];
    __syncthreads();
    float wt[25];
#pragma unroll
    for (int k = 0; k < 25; k++) wt[k] = wsh[k][c];
    const float lbv = lb[c];

    const float* xb = x + (size_t)b * HH * WW * CC + c;
    bool rv[5];
#pragma unroll
    for (int ky = 0; ky < 5; ky++) rv[ky] = (unsigned)(y + ky - 2) < (unsigned)HH;

    float win[5][5];
#pragma unroll
    for (int j = 0; j < 4; j++) {
        int col = x0 + j - 2;
        bool cv = (unsigned)col < (unsigned)WW;
#pragma unroll
        for (int ky = 0; ky < 5; ky++)
            win[j][ky] = (cv && rv[ky])
                ? xb[((size_t)(y + ky - 2) * WW + col) * CC] : 0.f;
    }

#pragma unroll
    for (int i = 0; i < XG; i++) {
        const int slot = (i + 4) % 5;
        int col = x0 + i + 2;
        bool cv = col < WW;
#pragma unroll
        for (int ky = 0; ky < 5; ky++)
            win[slot][ky] = (cv && rv[ky])
                ? xb[((size_t)(y + ky - 2) * WW + col) * CC] : 0.f;

        float sum = lbv;
#pragma unroll
        for (int kx = 0; kx < 5; kx++) {
            const int s = (i + kx) % 5;
#pragma unroll
            for (int ky = 0; ky < 5; ky++)
                sum += win[s][ky] * wt[ky * 5 + kx];
        }
        g_attn[((size_t)b * SS + 1 + y * WW + x0 + i) * CC + c] += sum;
    }
}

// ---------------------------------------------------------------------------
extern "C" void kernel_launch(void* const* d_in, const int* in_sizes, int n_in,
                              void* d_out, int out_size)
{
    const float* x      = (const float*)d_in[0];
    const float* cls    = (const float*)d_in[1];
    const float* qkv_w  = (const float*)d_in[2];
    const float* proj_w = (const float*)d_in[3];
    const float* proj_b = (const float*)d_in[4];
    const float* lepe_w = (const float*)d_in[5];
    const float* lepe_b = (const float*)d_in[6];

    float* out_x   = (float*)d_out;
    float* out_cls = (float*)d_out + in_sizes[0];

    // 0) exact fp32 V column sums (two-stage, wide)
    vsum_a_kernel<<<256, 256>>>(x);
    vsum_b_kernel<<<BB, 256>>>(cls, qkv_w);

    // 1) QKV projection on tensor cores -> fp16 Q (pre-scaled), K, V^T
    hgemm_kernel<<<dim3((MROWS + 127) / 128, 768 / 128), 256>>>(
        x, cls, qkv_w, nullptr, nullptr, nullptr, 0);

    // 2) fp16 mma.sync flash attention (QTILE=256, halved LDGSTS floor)
    attn_mma_kernel<<<dim3((SP + QTILE - 1) / QTILE, BHN), 512>>>();

    // 3) LePE depthwise conv added into g_attn (sliding window)
    lepe_kernel<<<dim3(WW / XG, HH, BB), 256>>>(x, lepe_w, lepe_b);

    // 4) Output projection on tensor cores
    hgemm_kernel<<<dim3((MROWS + 127) / 128, CC / 128), 256>>>(
        nullptr, nullptr, proj_w, proj_b, out_x, out_cls, 1);
}

// round 12
// speedup vs baseline: 1.0912x; 1.0912x over previous
#include <cuda_runtime.h>
#include <cuda_fp16.h>
#include <cstdint>

// Problem constants
#define BB   4
#define HH   56
#define WW   56
#define CC   256
#define NH   8
#define HD   32
#define NN   (HH*WW)          // 3136
#define SS   (NN + 1)         // 3137
#define SP   3200             // padded seq stride (25*128)
#define MROWS (BB * SS)       // 12548
#define BHN  (BB * NH)        // 32

// Scratch (device globals; zero-initialized — padding stays 0)
__device__ float g_attn[(size_t)BB * SS * CC];
__device__ __half g_q[(size_t)BHN * SP * HD];    // pre-scaled by 1/sqrt(hd)*log2(e)
__device__ __half g_k[(size_t)BHN * SP * HD];
__device__ __half g_vt[(size_t)BHN * HD * SP];   // V^T: [bh][d][s]
__device__ float  g_vsum[BB * CC];               // fp32 exact sum_s V[s][d] (b,h,d)
__device__ float  g_xpart[256][CC];              // partial column sums of x

// ---------------------------------------------------------------------------
// PTX helpers (baseline-PTX instructions only)
// ---------------------------------------------------------------------------
__device__ __forceinline__ uint32_t smem_u32(const void* p) {
    uint32_t a;
    asm("{ .reg .u64 t; cvta.to.shared.u64 t, %1; cvt.u32.u64 %0, t; }"
        : "=r"(a) : "l"(p));
    return a;
}
__device__ __forceinline__ void mma16816h(float* d, const uint32_t* a,
                                          const uint32_t* b, const float* c) {
    asm volatile(
        "mma.sync.aligned.m16n8k16.row.col.f32.f16.f16.f32 "
        "{%0,%1,%2,%3}, {%4,%5,%6,%7}, {%8,%9}, {%10,%11,%12,%13};"
        : "=f"(d[0]), "=f"(d[1]), "=f"(d[2]), "=f"(d[3])
        : "r"(a[0]), "r"(a[1]), "r"(a[2]), "r"(a[3]),
          "r"(b[0]), "r"(b[1]),
          "f"(c[0]), "f"(c[1]), "f"(c[2]), "f"(c[3]));
}
// f16-accumulator variant: D/C are 2 x f16x2 regs
__device__ __forceinline__ void mma16816hh(uint32_t* d, const uint32_t* a,
                                           const uint32_t* b, const uint32_t* c) {
    asm volatile(
        "mma.sync.aligned.m16n8k16.row.col.f16.f16.f16.f16 "
        "{%0,%1}, {%2,%3,%4,%5}, {%6,%7}, {%8,%9};"
        : "=r"(d[0]), "=r"(d[1])
        : "r"(a[0]), "r"(a[1]), "r"(a[2]), "r"(a[3]),
          "r"(b[0]), "r"(b[1]), "r"(c[0]), "r"(c[1]));
}
__device__ __forceinline__ void ldm4(uint32_t* r, uint32_t a) {
    asm volatile("ldmatrix.sync.aligned.m8n8.x4.shared.b16 {%0,%1,%2,%3}, [%4];"
                 : "=r"(r[0]), "=r"(r[1]), "=r"(r[2]), "=r"(r[3]) : "r"(a));
}
__device__ __forceinline__ float ex2(float x) {
    float r;
    asm("ex2.approx.ftz.f32 %0, %1;" : "=f"(r) : "f"(x));
    return r;
}
// pack two f32 -> f16x2 (lo half = first arg)
__device__ __forceinline__ uint32_t packh(float lo, float hi) {
    uint32_t r;
    asm("cvt.rn.f16x2.f32 %0, %1, %2;" : "=r"(r) : "f"(hi), "f"(lo));
    return r;
}
__device__ __forceinline__ uint32_t ex2h2(uint32_t s) {
    uint32_t r;
    asm("ex2.approx.f16x2 %0, %1;" : "=r"(r) : "r"(s));
    return r;
}
__device__ __forceinline__ uint32_t hsub2u(uint32_t a, uint32_t b) {
    uint32_t r;
    asm("sub.rn.f16x2 %0, %1, %2;" : "=r"(r) : "r"(a), "r"(b));
    return r;
}
__device__ __forceinline__ uint32_t hadd2u(uint32_t a, uint32_t b) {
    uint32_t r;
    asm("add.rn.f16x2 %0, %1, %2;" : "=r"(r) : "r"(a), "r"(b));
    return r;
}
#define CP16(dst, src) asm volatile("cp.async.cg.shared.global [%0], [%1], 16;" :: "r"(dst), "l"(src) : "memory")
#define CPCOMMIT()     asm volatile("cp.async.commit_group;" ::: "memory")
#define CPWAIT1()      asm volatile("cp.async.wait_group 1;" ::: "memory")

// ---------------------------------------------------------------------------
// fp16 tensor-core GEMM: C[M,N] = A[M,256] * W[N,256]^T (+bias)
// Block tile 128x128, 8 warps of 32x64. K staged 32/iter, fp32->fp16 in regs.
// mode 0: A = concat(cls, x); outputs fp16 Q (pre-scaled), K, V^T
// mode 1: A = g_attn; outputs -> d_out (x part / cls part) with bias
// ---------------------------------------------------------------------------
#define STA 40    // smem row stride in halves (80B) — ldmatrix conflict-free
__global__ __launch_bounds__(256, 2) void hgemm_kernel(
    const float* __restrict__ x, const float* __restrict__ cls,
    const float* __restrict__ w, const float* __restrict__ bias,
    float* __restrict__ out_x, float* __restrict__ out_cls, int mode)
{
    __shared__ alignas(16) uint16_t As[128 * STA];
    __shared__ alignas(16) uint16_t Bs[128 * STA];

    const int t    = threadIdx.x;
    const int wp   = t >> 5, lane = t & 31;
    const int wy   = wp >> 1, wx = wp & 1;
    const int g    = lane >> 2, m2 = (lane & 3) * 2;
    const int row0 = blockIdx.x * 128;
    const int col0 = blockIdx.y * 128;

    // staging: thread t handles row t>>1, 16-col half (t&1)
    const int sr = t >> 1;
    const int sc = (t & 1) * 16;

    const float* asrc = nullptr;
    {
        int arow = row0 + sr;
        if (arow < MROWS) {
            if (mode == 0) {
                int ab = arow / SS, asq = arow - ab * SS;
                asrc = (asq == 0) ? (cls + (size_t)ab * CC)
                                  : (x + ((size_t)ab * NN + (asq - 1)) * CC);
            } else {
                asrc = g_attn + (size_t)arow * CC;
            }
        }
    }
    const float* bsrc = w + (size_t)(col0 + sr) * CC + sc;

    // ldmatrix base addresses
    const uint32_t aaddr0 = smem_u32(As)
        + (uint32_t)(wy * 32 + (lane & 15)) * (STA * 2) + (lane >> 4) * 16;
    const uint32_t baddr0 = smem_u32(Bs)
        + (uint32_t)(wx * 64 + (lane & 7)) * (STA * 2) + (lane >> 3) * 16;

    float acc[2][8][4];
#pragma unroll
    for (int f = 0; f < 2; f++)
#pragma unroll
        for (int j = 0; j < 8; j++)
#pragma unroll
            for (int c = 0; c < 4; c++) acc[f][j][c] = 0.f;

    float4 abuf[4], bbuf[4];
    // prologue: load stage 0
#pragma unroll
    for (int q = 0; q < 4; q++) {
        abuf[q] = asrc ? *(const float4*)(asrc + sc + q * 4)
                       : make_float4(0.f, 0.f, 0.f, 0.f);
        bbuf[q] = *(const float4*)(bsrc + q * 4);
    }

    uint16_t* ap = As + sr * STA + sc;
    uint16_t* bp = Bs + sr * STA + sc;

    for (int st = 0; st < 8; st++) {
        // convert + store current stage
        {
            uint4 u0 = make_uint4(packh(abuf[0].x, abuf[0].y), packh(abuf[0].z, abuf[0].w),
                                  packh(abuf[1].x, abuf[1].y), packh(abuf[1].z, abuf[1].w));
            uint4 u1 = make_uint4(packh(abuf[2].x, abuf[2].y), packh(abuf[2].z, abuf[2].w),
                                  packh(abuf[3].x, abuf[3].y), packh(abuf[3].z, abuf[3].w));
            *(uint4*)ap = u0; *(uint4*)(ap + 8) = u1;
            uint4 v0 = make_uint4(packh(bbuf[0].x, bbuf[0].y), packh(bbuf[0].z, bbuf[0].w),
                                  packh(bbuf[1].x, bbuf[1].y), packh(bbuf[1].z, bbuf[1].w));
            uint4 v1 = make_uint4(packh(bbuf[2].x, bbuf[2].y), packh(bbuf[2].z, bbuf[2].w),
                                  packh(bbuf[3].x, bbuf[3].y), packh(bbuf[3].z, bbuf[3].w));
            *(uint4*)bp = v0; *(uint4*)(bp + 8) = v1;
        }
        __syncthreads();

        // prefetch next stage (overlaps MMA)
        if (st < 7) {
            int off = (st + 1) * 32 + sc;
#pragma unroll
            for (int q = 0; q < 4; q++) {
                abuf[q] = asrc ? *(const float4*)(asrc + off + q * 4)
                               : make_float4(0.f, 0.f, 0.f, 0.f);
                bbuf[q] = *(const float4*)(bsrc + (st + 1) * 32 + q * 4);
            }
        }

        // MMA: 2 M-frags x 2 k-chunks x 8 n-chunks
        uint32_t af[2][2][4];
#pragma unroll
        for (int f = 0; f < 2; f++)
#pragma unroll
            for (int c = 0; c < 2; c++)
                ldm4(af[f][c], aaddr0 + f * (16 * STA * 2) + c * 32);
#pragma unroll
        for (int jn = 0; jn < 8; jn++) {
            uint32_t bf[4];
            ldm4(bf, baddr0 + jn * (8 * STA * 2));
            mma16816h(acc[0][jn], af[0][0], bf + 0, acc[0][jn]);
            mma16816h(acc[0][jn], af[0][1], bf + 2, acc[0][jn]);
            mma16816h(acc[1][jn], af[1][0], bf + 0, acc[1][jn]);
            mma16816h(acc[1][jn], af[1][1], bf + 2, acc[1][jn]);
        }
        __syncthreads();
    }

    // epilogue
    const float QSCALE = 0.17677669529663687f * 1.4426950408889634f;
#pragma unroll
    for (int f = 0; f < 2; f++) {
#pragma unroll
        for (int half = 0; half < 2; half++) {
            int row = row0 + wy * 32 + f * 16 + g + half * 8;
            if (row >= MROWS) continue;
            int b = row / SS, s = row - b * SS;
#pragma unroll
            for (int jn = 0; jn < 8; jn++) {
                int n = col0 + wx * 64 + jn * 8 + m2;
                float v0 = acc[f][jn][half * 2 + 0];
                float v1 = acc[f][jn][half * 2 + 1];
                if (mode == 0) {
                    int c3 = n >> 8, rem = n & 255;
                    int h = rem >> 5, d = rem & 31;
                    int bh = b * NH + h;
                    if (c3 == 0) {
                        *(__half2*)&g_q[((size_t)bh * SP + s) * HD + d] =
                            __floats2half2_rn(v0 * QSCALE, v1 * QSCALE);
                    } else if (c3 == 1) {
                        *(__half2*)&g_k[((size_t)bh * SP + s) * HD + d] =
                            __floats2half2_rn(v0, v1);
                    } else {
                        g_vt[((size_t)bh * HD + d) * SP + s]     = __float2half(v0);
                        g_vt[((size_t)bh * HD + d + 1) * SP + s] = __float2half(v1);
                    }
                } else {
                    v0 += bias[n]; v1 += bias[n + 1];
                    if (s == 0)
                        *(float2*)&out_cls[(size_t)b * CC + n] = make_float2(v0, v1);
                    else
                        *(float2*)&out_x[((size_t)b * NN + (s - 1)) * CC + n] =
                            make_float2(v0, v1);
                }
            }
        }
    }
}

// ---------------------------------------------------------------------------
// V column sums, two-stage (wide)
// ---------------------------------------------------------------------------
__global__ __launch_bounds__(256) void vsum_a_kernel(const float* __restrict__ x)
{
    const int blk = blockIdx.x;          // b*64 + chunk
    const int b   = blk >> 6, ch = blk & 63;
    const int c   = threadIdx.x;
    const float* p = x + ((size_t)b * NN + ch * 49) * CC + c;
    float s = 0.f;
#pragma unroll 7
    for (int r = 0; r < 49; r++) s += p[(size_t)r * CC];
    g_xpart[blk][c] = s;
}

__global__ __launch_bounds__(256) void vsum_b_kernel(
    const float* __restrict__ cls, const float* __restrict__ qkv_w)
{
    __shared__ float xs[256];
    const int b = blockIdx.x;
    const int t = threadIdx.x;
    float s = cls[b * CC + t];
#pragma unroll
    for (int k = 0; k < 64; k++) s += g_xpart[b * 64 + k][t];
    xs[t] = s;
    __syncthreads();
    const float* wr = qkv_w + (size_t)(2 * CC + t) * CC;   // Wv row t
    float acc = 0.f;
#pragma unroll 8
    for (int cc = 0; cc < CC; cc++) acc += xs[cc] * wr[cc];
    g_vsum[b * CC + t] = acc;
}

// ---------------------------------------------------------------------------
// Flash attention, fp16 mma.sync, mean-subtracted PV.
// S-GEMM uses f16 ACCUMULATORS: the C-fragment lands as f16x2 pairs that feed
// ex2.approx.f16x2 directly (no packing) -> shorter epilogue chain + fewer
// registers -> 3 CTAs/SM. O stays fp32. 256 threads, QTILE=128, TKEY=64.
// ---------------------------------------------------------------------------
#define TKEY 64
#define QTILE 128
#define STK 40
#define STV 72
#define KT_TILES (SP / TKEY)     // 50
#define MASK_FROM (SS / TKEY)    // 49

__global__ __launch_bounds__(256, 3) void attn_mma_kernel()
{
    __shared__ alignas(16) uint16_t Kbuf[2][64 * STK];
    __shared__ alignas(16) uint16_t Vbuf[2][32 * STV];

    const int t    = threadIdx.x;
    const int w    = t >> 5;
    const int lane = t & 31;
    const int g    = lane >> 2;
    const int m2   = (lane & 3) * 2;
    const int bh   = blockIdx.y;
    const int q0   = blockIdx.x * QTILE;
    const int qrow = q0 + w * 16;

    // cp.async staging (2 x 16B per thread per tile)
    const int kr = t >> 2, kc4 = t & 3;
    const int vr = t >> 3, vc8 = t & 7;
    const __half* gk = g_k + (size_t)bh * SP * HD;
    const __half* gv = g_vt + (size_t)bh * HD * SP + (size_t)vr * SP;
    uint32_t kdst[2], vdst[2];
    kdst[0] = smem_u32(&Kbuf[0][kr * STK + kc4 * 8]);
    kdst[1] = smem_u32(&Kbuf[1][kr * STK + kc4 * 8]);
    vdst[0] = smem_u32(&Vbuf[0][vr * STV + vc8 * 8]);
    vdst[1] = smem_u32(&Vbuf[1][vr * STV + vc8 * 8]);

    uint32_t kmat[2], vmat[2];
    {
        uint32_t ko = ((lane & 7) * STK + (lane >> 3) * 8) * 2;
        uint32_t vo = ((lane & 7) * STV + (lane >> 3) * 8) * 2;
        kmat[0] = smem_u32(Kbuf[0]) + ko; kmat[1] = smem_u32(Kbuf[1]) + ko;
        vmat[0] = smem_u32(Vbuf[0]) + vo; vmat[1] = smem_u32(Vbuf[1]) + vo;
    }

    // Q fragments (rows beyond SS read zero padding)
    uint32_t qa[2][4];
    {
        const __half* qb = g_q + (size_t)bh * SP * HD;
        int r0 = qrow + g, r1 = qrow + g + 8;
#pragma unroll
        for (int kc = 0; kc < 2; kc++) {
            int d0 = kc * 16 + m2, d1 = d0 + 8;
            qa[kc][0] = *(const uint32_t*)(qb + (size_t)r0 * HD + d0);
            qa[kc][1] = *(const uint32_t*)(qb + (size_t)r1 * HD + d0);
            qa[kc][2] = *(const uint32_t*)(qb + (size_t)r0 * HD + d1);
            qa[kc][3] = *(const uint32_t*)(qb + (size_t)r1 * HD + d1);
        }
    }

    float o[4][4];
#pragma unroll
    for (int i = 0; i < 4; i++)
#pragma unroll
        for (int j = 0; j < 4; j++) o[i][j] = 0.f;
    float la = 0.f, lb = 0.f;
    const uint32_t ONE2 = 0x3C003C00u;   // half2(1, 1)

    // prologue: prefetch tile 0
    {
        CP16(kdst[0], gk + (size_t)kr * HD + kc4 * 8);
        CP16(vdst[0], gv + vc8 * 8);
        CPCOMMIT();
    }

    for (int kt = 0; kt < KT_TILES; kt++) {
        const int cur = kt & 1;
        __syncthreads();
        if (kt + 1 < KT_TILES) {
            int nk = kt + 1;
            CP16(cur ? kdst[0] : kdst[1], gk + (size_t)(nk * TKEY + kr) * HD + kc4 * 8);
            CP16(cur ? vdst[0] : vdst[1], gv + nk * TKEY + vc8 * 8);
        }
        CPCOMMIT();
        CPWAIT1();
        __syncthreads();

        // ---- S = Q K^T : f16 accumulators (C-frag = 2 x f16x2) ----
        uint32_t sh[8][2];
#pragma unroll
        for (int jn = 0; jn < 8; jn++) {
            uint32_t kb4[4];
            ldm4(kb4, kmat[cur] + jn * (8 * STK * 2));
            sh[jn][0] = 0u; sh[jn][1] = 0u;
            mma16816hh(sh[jn], qa[0], kb4 + 0, sh[jn]);
            mma16816hh(sh[jn], qa[1], kb4 + 2, sh[jn]);
        }

        // ---- p = exp2(s) straight from f16x2 frags; f = p-1; l tree ----
        uint32_t fh[8][2];
        if (kt < MASK_FROM) {
            uint32_t t01[8], t23[8];
#pragma unroll
            for (int jn = 0; jn < 8; jn++) {
                uint32_t p01 = ex2h2(sh[jn][0]);
                uint32_t p23 = ex2h2(sh[jn][1]);
                fh[jn][0] = hsub2u(p01, ONE2);
                fh[jn][1] = hsub2u(p23, ONE2);
                t01[jn] = p01; t23[jn] = p23;
            }
            uint32_t a0 = hadd2u(hadd2u(t01[0], t01[1]), hadd2u(t01[2], t01[3]));
            uint32_t a1 = hadd2u(hadd2u(t01[4], t01[5]), hadd2u(t01[6], t01[7]));
            uint32_t b0 = hadd2u(hadd2u(t23[0], t23[1]), hadd2u(t23[2], t23[3]));
            uint32_t b1 = hadd2u(hadd2u(t23[4], t23[5]), hadd2u(t23[6], t23[7]));
            a0 = hadd2u(a0, a1);
            b0 = hadd2u(b0, b1);
            __half2 ha = *(__half2*)&a0;
            __half2 hb = *(__half2*)&b0;
            la += __low2float(ha) + __high2float(ha);
            lb += __low2float(hb) + __high2float(hb);
        } else {
            // padded-key tiles: exact scalar path with column masking
            const int kb = kt * TKEY;
#pragma unroll
            for (int jn = 0; jn < 8; jn++) {
                int col0 = kb + jn * 8 + m2;
                bool c0v = col0 < SS, c1v = (col0 + 1) < SS;
                float2 s01 = __half22float2(*(__half2*)&sh[jn][0]);
                float2 s23 = __half22float2(*(__half2*)&sh[jn][1]);
                float p0 = c0v ? ex2(s01.x) : 0.f;
                float p1 = c1v ? ex2(s01.y) : 0.f;
                float p2 = c0v ? ex2(s23.x) : 0.f;
                float p3 = c1v ? ex2(s23.y) : 0.f;
                la += p0 + p1;
                lb += p2 + p3;
                fh[jn][0] = packh(c0v ? (p0 - 1.f) : 0.f, c1v ? (p1 - 1.f) : 0.f);
                fh[jn][1] = packh(c0v ? (p2 - 1.f) : 0.f, c1v ? (p3 - 1.f) : 0.f);
            }
        }

        // ---- O += F V : fp32 accumulators ----
        uint32_t pa[4][4];
#pragma unroll
        for (int kc2 = 0; kc2 < 4; kc2++) {
            pa[kc2][0] = fh[2 * kc2][0];
            pa[kc2][1] = fh[2 * kc2][1];
            pa[kc2][2] = fh[2 * kc2 + 1][0];
            pa[kc2][3] = fh[2 * kc2 + 1][1];
        }
#pragma unroll
        for (int jn2 = 0; jn2 < 4; jn2++) {
            uint32_t vv[8];
            ldm4(vv,     vmat[cur] + jn2 * (8 * STV * 2));
            ldm4(vv + 4, vmat[cur] + jn2 * (8 * STV * 2) + 64);
#pragma unroll
            for (int kc2 = 0; kc2 < 4; kc2++)
                mma16816h(o[jn2], pa[kc2], vv + 2 * kc2, o[jn2]);
        }
    }

    // ---- reduce l over quad, add Vsum, normalize, store ----
    la += __shfl_xor_sync(0xffffffffu, la, 1);
    la += __shfl_xor_sync(0xffffffffu, la, 2);
    lb += __shfl_xor_sync(0xffffffffu, lb, 1);
    lb += __shfl_xor_sync(0xffffffffu, lb, 2);
    const float ia = 1.f / la, ib = 1.f / lb;

    const int b = bh >> 3;
    const int h = bh & 7;
    const int r0 = qrow + g, r1 = qrow + g + 8;
#pragma unroll
    for (int jn2 = 0; jn2 < 4; jn2++) {
        float2 vs = *(const float2*)&g_vsum[b * CC + h * HD + jn2 * 8 + m2];
        if (r0 < SS) {
            float* dst = g_attn + ((size_t)b * SS + r0) * CC + h * HD + jn2 * 8 + m2;
            *(float2*)dst = make_float2((o[jn2][0] + vs.x) * ia,
                                        (o[jn2][1] + vs.y) * ia);
        }
        if (r1 < SS) {
            float* dst = g_attn + ((size_t)b * SS + r1) * CC + h * HD + jn2 * 8 + m2;
            *(float2*)dst = make_float2((o[jn2][2] + vs.x) * ib,
                                        (o[jn2][3] + vs.y) * ib);
        }
    }
}

// ---------------------------------------------------------------------------
// LePE: 5x5 depthwise conv (SAME), sliding-window version (unchanged)
// ---------------------------------------------------------------------------
#define XG 14
__global__ __launch_bounds__(256) void lepe_kernel(
    const float* __restrict__ x, const float* __restrict__ lw,
    const float* __restrict__ lb)
{
    __shared__ float wsh[25][256];
    const int c  = threadIdx.x;
    const int x0 = blockIdx.x * XG;
    const int y  = blockIdx.y;
    const int b  = blockIdx.z;

    for (int i = c; i < 25 * 256; i += 256)
        wsh[i % 25][i / 25] = lw[i];
    __syncthreads();
    float wt[25];
#pragma unroll
    for (int k = 0; k < 25; k++) wt[k] = wsh[k][c];
    const float lbv = lb[c];

    const float* xb = x + (size_t)b * HH * WW * CC + c;
    bool rv[5];
#pragma unroll
    for (int ky = 0; ky < 5; ky++) rv[ky] = (unsigned)(y + ky - 2) < (unsigned)HH;

    float win[5][5];
#pragma unroll
    for (int j = 0; j < 4; j++) {
        int col = x0 + j - 2;
        bool cv = (unsigned)col < (unsigned)WW;
#pragma unroll
        for (int ky = 0; ky < 5; ky++)
            win[j][ky] = (cv && rv[ky])
                ? xb[((size_t)(y + ky - 2) * WW + col) * CC] : 0.f;
    }

#pragma unroll
    for (int i = 0; i < XG; i++) {
        const int slot = (i + 4) % 5;
        int col = x0 + i + 2;
        bool cv = col < WW;
#pragma unroll
        for (int ky = 0; ky < 5; ky++)
            win[slot][ky] = (cv && rv[ky])
                ? xb[((size_t)(y + ky - 2) * WW + col) * CC] : 0.f;

        float sum = lbv;
#pragma unroll
        for (int kx = 0; kx < 5; kx++) {
            const int s = (i + kx) % 5;
#pragma unroll
            for (int ky = 0; ky < 5; ky++)
                sum += win[s][ky] * wt[ky * 5 + kx];
        }
        g_attn[((size_t)b * SS + 1 + y * WW + x0 + i) * CC + c] += sum;
    }
}

// ---------------------------------------------------------------------------
extern "C" void kernel_launch(void* const* d_in, const int* in_sizes, int n_in,
                              void* d_out, int out_size)
{
    const float* x      = (const float*)d_in[0];
    const float* cls    = (const float*)d_in[1];
    const float* qkv_w  = (const float*)d_in[2];
    const float* proj_w = (const float*)d_in[3];
    const float* proj_b = (const float*)d_in[4];
    const float* lepe_w = (const float*)d_in[5];
    const float* lepe_b = (const float*)d_in[6];

    float* out_x   = (float*)d_out;
    float* out_cls = (float*)d_out + in_sizes[0];

    // 0) exact fp32 V column sums (two-stage, wide)
    vsum_a_kernel<<<256, 256>>>(x);
    vsum_b_kernel<<<BB, 256>>>(cls, qkv_w);

    // 1) QKV projection on tensor cores -> fp16 Q (pre-scaled), K, V^T
    hgemm_kernel<<<dim3((MROWS + 127) / 128, 768 / 128), 256>>>(
        x, cls, qkv_w, nullptr, nullptr, nullptr, 0);

    // 2) fp16 mma.sync flash attention (f16-acc S GEMM, 3 CTAs/SM)
    attn_mma_kernel<<<dim3(SP / QTILE, BHN), 256>>>();

    // 3) LePE depthwise conv added into g_attn (sliding window)
    lepe_kernel<<<dim3(WW / XG, HH, BB), 256>>>(x, lepe_w, lepe_b);

    // 4) Output projection on tensor cores
    hgemm_kernel<<<dim3((MROWS + 127) / 128, CC / 128), 256>>>(
        nullptr, nullptr, proj_w, proj_b, out_x, out_cls, 1);
}

// round 13
// speedup vs baseline: 1.1846x; 1.0856x over previous
#include <cuda_runtime.h>
#include <cuda_fp16.h>
#include <cstdint>

// Problem constants
#define BB   4
#define HH   56
#define WW   56
#define CC   256
#define NH   8
#define HD   32
#define NN   (HH*WW)          // 3136
#define SS   (NN + 1)         // 3137
#define SP   3200             // padded seq stride (25*128)
#define MROWS (BB * SS)       // 12548
#define BHN  (BB * NH)        // 32

// Scratch (device globals; zero-initialized — padding stays 0)
__device__ __half g_attnh[(size_t)BB * SS * CC];   // attention out (+lepe), fp16
__device__ __half g_xh[(size_t)MROWS * CC];        // fp16 concat(cls,x), GEMM rows
__device__ __half g_wqkv[768 * CC];                // fp16 qkv_w
__device__ __half g_wproj[CC * CC];                // fp16 proj_w
__device__ __half g_q[(size_t)BHN * SP * HD];      // pre-scaled by 1/sqrt(hd)*log2(e)
__device__ __half g_k[(size_t)BHN * SP * HD];
__device__ __half g_vt[(size_t)BHN * HD * SP];     // V^T: [bh][d][s]
__device__ float  g_vsum[BB * CC];                 // fp32 exact sum_s V[s][d]
__device__ float  g_xpart[256][CC];                // partial column sums of x

// ---------------------------------------------------------------------------
// PTX helpers (baseline-PTX instructions only)
// ---------------------------------------------------------------------------
__device__ __forceinline__ uint32_t smem_u32(const void* p) {
    uint32_t a;
    asm("{ .reg .u64 t; cvta.to.shared.u64 t, %1; cvt.u32.u64 %0, t; }"
        : "=r"(a) : "l"(p));
    return a;
}
__device__ __forceinline__ void mma16816h(float* d, const uint32_t* a,
                                          const uint32_t* b, const float* c) {
    asm volatile(
        "mma.sync.aligned.m16n8k16.row.col.f32.f16.f16.f32 "
        "{%0,%1,%2,%3}, {%4,%5,%6,%7}, {%8,%9}, {%10,%11,%12,%13};"
        : "=f"(d[0]), "=f"(d[1]), "=f"(d[2]), "=f"(d[3])
        : "r"(a[0]), "r"(a[1]), "r"(a[2]), "r"(a[3]),
          "r"(b[0]), "r"(b[1]),
          "f"(c[0]), "f"(c[1]), "f"(c[2]), "f"(c[3]));
}
// f16-accumulator variant: D/C are 2 x f16x2 regs
__device__ __forceinline__ void mma16816hh(uint32_t* d, const uint32_t* a,
                                           const uint32_t* b, const uint32_t* c) {
    asm volatile(
        "mma.sync.aligned.m16n8k16.row.col.f16.f16.f16.f16 "
        "{%0,%1}, {%2,%3,%4,%5}, {%6,%7}, {%8,%9};"
        : "=r"(d[0]), "=r"(d[1])
        : "r"(a[0]), "r"(a[1]), "r"(a[2]), "r"(a[3]),
          "r"(b[0]), "r"(b[1]), "r"(c[0]), "r"(c[1]));
}
__device__ __forceinline__ void ldm4(uint32_t* r, uint32_t a) {
    asm volatile("ldmatrix.sync.aligned.m8n8.x4.shared.b16 {%0,%1,%2,%3}, [%4];"
                 : "=r"(r[0]), "=r"(r[1]), "=r"(r[2]), "=r"(r[3]) : "r"(a));
}
__device__ __forceinline__ float ex2(float x) {
    float r;
    asm("ex2.approx.ftz.f32 %0, %1;" : "=f"(r) : "f"(x));
    return r;
}
__device__ __forceinline__ uint32_t packh(float lo, float hi) {
    uint32_t r;
    asm("cvt.rn.f16x2.f32 %0, %1, %2;" : "=r"(r) : "f"(hi), "f"(lo));
    return r;
}
__device__ __forceinline__ uint32_t ex2h2(uint32_t s) {
    uint32_t r;
    asm("ex2.approx.f16x2 %0, %1;" : "=r"(r) : "r"(s));
    return r;
}
__device__ __forceinline__ uint32_t hsub2u(uint32_t a, uint32_t b) {
    uint32_t r;
    asm("sub.rn.f16x2 %0, %1, %2;" : "=r"(r) : "r"(a), "r"(b));
    return r;
}
__device__ __forceinline__ uint32_t hadd2u(uint32_t a, uint32_t b) {
    uint32_t r;
    asm("add.rn.f16x2 %0, %1, %2;" : "=r"(r) : "r"(a), "r"(b));
    return r;
}
__device__ __forceinline__ uint32_t hmul2u(uint32_t a, uint32_t b) {
    uint32_t r;
    asm("mul.rn.f16x2 %0, %1, %2;" : "=r"(r) : "r"(a), "r"(b));
    return r;
}
#define CP16(dst, src)      asm volatile("cp.async.cg.shared.global [%0], [%1], 16;" :: "r"(dst), "l"(src) : "memory")
#define CP16Z(dst, src, sz) asm volatile("cp.async.cg.shared.global [%0], [%1], 16, %2;" :: "r"(dst), "l"(src), "r"(sz) : "memory")
#define CPCOMMIT()          asm volatile("cp.async.commit_group;" ::: "memory")
#define CPWAIT1()           asm volatile("cp.async.wait_group 1;" ::: "memory")

// ---------------------------------------------------------------------------
// vsum_a: partial column sums of x + fp16 conversion of x and weights.
// 256 blocks x 256 threads.
// ---------------------------------------------------------------------------
__global__ __launch_bounds__(256) void vsum_a_kernel(
    const float* __restrict__ x, const float* __restrict__ qkv_w,
    const float* __restrict__ proj_w)
{
    const int blk = blockIdx.x;          // b*64 + chunk
    const int b   = blk >> 6, ch = blk & 63;
    const int c   = threadIdx.x;
    const float* p = x + ((size_t)b * NN + ch * 49) * CC + c;
    __half* xo = g_xh + ((size_t)b * SS + 1 + ch * 49) * CC + c;
    float s = 0.f;
#pragma unroll 7
    for (int r = 0; r < 49; r++) {
        float v = p[(size_t)r * CC];
        s += v;
        xo[(size_t)r * CC] = __float2half(v);
    }
    g_xpart[blk][c] = s;

    // weight conversion: threads 0..49151 -> qkv_w (4 each), rest -> proj_w
    int idx = blk * 256 + c;
    if (idx < 49152) {
        const float4 wv = *(const float4*)(qkv_w + idx * 4);
        *(uint2*)&g_wqkv[idx * 4] =
            make_uint2(packh(wv.x, wv.y), packh(wv.z, wv.w));
    } else {
        int e = idx - 49152;
        const float4 wv = *(const float4*)(proj_w + e * 4);
        *(uint2*)&g_wproj[e * 4] =
            make_uint2(packh(wv.x, wv.y), packh(wv.z, wv.w));
    }
}

__global__ __launch_bounds__(256) void vsum_b_kernel(
    const float* __restrict__ cls, const float* __restrict__ qkv_w)
{
    __shared__ float xs[256];
    const int b = blockIdx.x;
    const int t = threadIdx.x;
    float cv = cls[b * CC + t];
    g_xh[(size_t)b * SS * CC + t] = __float2half(cv);   // cls GEMM row
    float s = cv;
#pragma unroll
    for (int k = 0; k < 64; k++) s += g_xpart[b * 64 + k][t];
    xs[t] = s;
    __syncthreads();
    const float* wr = qkv_w + (size_t)(2 * CC + t) * CC;   // Wv row t
    float acc = 0.f;
#pragma unroll 8
    for (int cc = 0; cc < CC; cc++) acc += xs[cc] * wr[cc];
    g_vsum[b * CC + t] = acc;
}

// ---------------------------------------------------------------------------
// QKV GEMM, all-fp16 (f16 accumulators), cp.async staging, 3 CTAs/SM.
// C[M,768] = g_xh[M,256] * g_wqkv[768,256]^T -> Q (scaled), K, V^T
// ---------------------------------------------------------------------------
#define STA 40    // smem row stride in halves (80B) — ldmatrix conflict-free
__global__ __launch_bounds__(256, 3) void hgemm_qkv_kernel()
{
    __shared__ alignas(16) uint16_t As[2][128 * STA];
    __shared__ alignas(16) uint16_t Bs[2][128 * STA];

    const int t    = threadIdx.x;
    const int wp   = t >> 5, lane = t & 31;
    const int wy   = wp >> 1, wx = wp & 1;
    const int g    = lane >> 2, m2 = (lane & 3) * 2;
    const int row0 = blockIdx.x * 128;
    const int col0 = blockIdx.y * 128;

    const int sr = t >> 1;
    const int sc = (t & 1) * 16;
    const int arow = row0 + sr;
    const uint32_t szA = (arow < MROWS) ? 16u : 0u;
    const __half* asrc = g_xh + (size_t)(szA ? arow : 0) * CC + sc;
    const __half* bsrc = g_wqkv + (size_t)(col0 + sr) * CC + sc;

    uint32_t adst[2], bdst[2];
    adst[0] = smem_u32(&As[0][sr * STA + sc]);
    adst[1] = smem_u32(&As[1][sr * STA + sc]);
    bdst[0] = smem_u32(&Bs[0][sr * STA + sc]);
    bdst[1] = smem_u32(&Bs[1][sr * STA + sc]);

    uint32_t aaddr[2], baddr[2];
    {
        uint32_t ao = (uint32_t)(wy * 32 + (lane & 15)) * (STA * 2) + (lane >> 4) * 16;
        uint32_t bo = (uint32_t)(wx * 64 + (lane & 7)) * (STA * 2) + (lane >> 3) * 16;
        aaddr[0] = smem_u32(As[0]) + ao; aaddr[1] = smem_u32(As[1]) + ao;
        baddr[0] = smem_u32(Bs[0]) + bo; baddr[1] = smem_u32(Bs[1]) + bo;
    }

    uint32_t acc[2][8][2];
#pragma unroll
    for (int f = 0; f < 2; f++)
#pragma unroll
        for (int j = 0; j < 8; j++) { acc[f][j][0] = 0u; acc[f][j][1] = 0u; }

    // prologue: stage 0
    CP16Z(adst[0], asrc, szA);
    CP16Z(adst[0] + 16, asrc + 8, szA);
    CP16(bdst[0], bsrc);
    CP16(bdst[0] + 16, bsrc + 8);
    CPCOMMIT();

    for (int st = 0; st < 8; st++) {
        const int cur = st & 1;
        __syncthreads();
        if (st < 7) {
            const __half* an = asrc + (st + 1) * 32;
            const __half* bn = bsrc + (st + 1) * 32;
            CP16Z(adst[cur ^ 1], an, szA);
            CP16Z(adst[cur ^ 1] + 16, an + 8, szA);
            CP16(bdst[cur ^ 1], bn);
            CP16(bdst[cur ^ 1] + 16, bn + 8);
        }
        CPCOMMIT();
        CPWAIT1();
        __syncthreads();

        uint32_t af[2][2][4];
#pragma unroll
        for (int f = 0; f < 2; f++)
#pragma unroll
            for (int c = 0; c < 2; c++)
                ldm4(af[f][c], aaddr[cur] + f * (16 * STA * 2) + c * 32);
#pragma unroll
        for (int jn = 0; jn < 8; jn++) {
            uint32_t bf[4];
            ldm4(bf, baddr[cur] + jn * (8 * STA * 2));
            mma16816hh(acc[0][jn], af[0][0], bf + 0, acc[0][jn]);
            mma16816hh(acc[0][jn], af[0][1], bf + 2, acc[0][jn]);
            mma16816hh(acc[1][jn], af[1][0], bf + 0, acc[1][jn]);
            mma16816hh(acc[1][jn], af[1][1], bf + 2, acc[1][jn]);
        }
    }

    // epilogue: scatter f16 pairs to Q (scaled) / K / V^T
    const uint32_t QS2 = packh(0.25505277f, 0.25505277f);  // 1/sqrt(32)*log2(e)
#pragma unroll
    for (int f = 0; f < 2; f++) {
#pragma unroll
        for (int half = 0; half < 2; half++) {
            int row = row0 + wy * 32 + f * 16 + g + half * 8;
            if (row >= MROWS) continue;
            int b = row / SS, s = row - b * SS;
#pragma unroll
            for (int jn = 0; jn < 8; jn++) {
                int n = col0 + wx * 64 + jn * 8 + m2;
                uint32_t pr = acc[f][jn][half];
                int c3 = n >> 8, rem = n & 255;
                int h = rem >> 5, d = rem & 31;
                int bh = b * NH + h;
                if (c3 == 0) {
                    *(uint32_t*)&g_q[((size_t)bh * SP + s) * HD + d] = hmul2u(pr, QS2);
                } else if (c3 == 1) {
                    *(uint32_t*)&g_k[((size_t)bh * SP + s) * HD + d] = pr;
                } else {
                    __half2 v2 = *(__half2*)&pr;
                    g_vt[((size_t)bh * HD + d) * SP + s]     = __low2half(v2);
                    g_vt[((size_t)bh * HD + d + 1) * SP + s] = __high2half(v2);
                }
            }
        }
    }
}

// ---------------------------------------------------------------------------
// Proj GEMM: fp32 accumulators, fp16 inputs (g_attnh, g_wproj), cp.async.
// ---------------------------------------------------------------------------
__global__ __launch_bounds__(256, 2) void hgemm_proj_kernel(
    const float* __restrict__ bias,
    float* __restrict__ out_x, float* __restrict__ out_cls)
{
    __shared__ alignas(16) uint16_t As[2][128 * STA];
    __shared__ alignas(16) uint16_t Bs[2][128 * STA];

    const int t    = threadIdx.x;
    const int wp   = t >> 5, lane = t & 31;
    const int wy   = wp >> 1, wx = wp & 1;
    const int g    = lane >> 2, m2 = (lane & 3) * 2;
    const int row0 = blockIdx.x * 128;
    const int col0 = blockIdx.y * 128;

    const int sr = t >> 1;
    const int sc = (t & 1) * 16;
    const int arow = row0 + sr;
    const uint32_t szA = (arow < MROWS) ? 16u : 0u;
    const __half* asrc = g_attnh + (size_t)(szA ? arow : 0) * CC + sc;
    const __half* bsrc = g_wproj + (size_t)(col0 + sr) * CC + sc;

    uint32_t adst[2], bdst[2];
    adst[0] = smem_u32(&As[0][sr * STA + sc]);
    adst[1] = smem_u32(&As[1][sr * STA + sc]);
    bdst[0] = smem_u32(&Bs[0][sr * STA + sc]);
    bdst[1] = smem_u32(&Bs[1][sr * STA + sc]);

    uint32_t aaddr[2], baddr[2];
    {
        uint32_t ao = (uint32_t)(wy * 32 + (lane & 15)) * (STA * 2) + (lane >> 4) * 16;
        uint32_t bo = (uint32_t)(wx * 64 + (lane & 7)) * (STA * 2) + (lane >> 3) * 16;
        aaddr[0] = smem_u32(As[0]) + ao; aaddr[1] = smem_u32(As[1]) + ao;
        baddr[0] = smem_u32(Bs[0]) + bo; baddr[1] = smem_u32(Bs[1]) + bo;
    }

    float acc[2][8][4];
#pragma unroll
    for (int f = 0; f < 2; f++)
#pragma unroll
        for (int j = 0; j < 8; j++)
#pragma unroll
            for (int c = 0; c < 4; c++) acc[f][j][c] = 0.f;

    CP16Z(adst[0], asrc, szA);
    CP16Z(adst[0] + 16, asrc + 8, szA);
    CP16(bdst[0], bsrc);
    CP16(bdst[0] + 16, bsrc + 8);
    CPCOMMIT();

    for (int st = 0; st < 8; st++) {
        const int cur = st & 1;
        __syncthreads();
        if (st < 7) {
            const __half* an = asrc + (st + 1) * 32;
            const __half* bn = bsrc + (st + 1) * 32;
            CP16Z(adst[cur ^ 1], an, szA);
            CP16Z(adst[cur ^ 1] + 16, an + 8, szA);
            CP16(bdst[cur ^ 1], bn);
            CP16(bdst[cur ^ 1] + 16, bn + 8);
        }
        CPCOMMIT();
        CPWAIT1();
        __syncthreads();

        uint32_t af[2][2][4];
#pragma unroll
        for (int f = 0; f < 2; f++)
#pragma unroll
            for (int c = 0; c < 2; c++)
                ldm4(af[f][c], aaddr[cur] + f * (16 * STA * 2) + c * 32);
#pragma unroll
        for (int jn = 0; jn < 8; jn++) {
            uint32_t bf[4];
            ldm4(bf, baddr[cur] + jn * (8 * STA * 2));
            mma16816h(acc[0][jn], af[0][0], bf + 0, acc[0][jn]);
            mma16816h(acc[0][jn], af[0][1], bf + 2, acc[0][jn]);
            mma16816h(acc[1][jn], af[1][0], bf + 0, acc[1][jn]);
            mma16816h(acc[1][jn], af[1][1], bf + 2, acc[1][jn]);
        }
    }

#pragma unroll
    for (int f = 0; f < 2; f++) {
#pragma unroll
        for (int half = 0; half < 2; half++) {
            int row = row0 + wy * 32 + f * 16 + g + half * 8;
            if (row >= MROWS) continue;
            int b = row / SS, s = row - b * SS;
#pragma unroll
            for (int jn = 0; jn < 8; jn++) {
                int n = col0 + wx * 64 + jn * 8 + m2;
                float v0 = acc[f][jn][half * 2 + 0] + bias[n];
                float v1 = acc[f][jn][half * 2 + 1] + bias[n + 1];
                if (s == 0)
                    *(float2*)&out_cls[(size_t)b * CC + n] = make_float2(v0, v1);
                else
                    *(float2*)&out_x[((size_t)b * NN + (s - 1)) * CC + n] =
                        make_float2(v0, v1);
            }
        }
    }
}

// ---------------------------------------------------------------------------
// Flash attention (unchanged from R12 except f16 output to g_attnh)
// ---------------------------------------------------------------------------
#define TKEY 64
#define QTILE 128
#define STK 40
#define STV 72
#define KT_TILES (SP / TKEY)     // 50
#define MASK_FROM (SS / TKEY)    // 49

__global__ __launch_bounds__(256, 3) void attn_mma_kernel()
{
    __shared__ alignas(16) uint16_t Kbuf[2][64 * STK];
    __shared__ alignas(16) uint16_t Vbuf[2][32 * STV];

    const int t    = threadIdx.x;
    const int w    = t >> 5;
    const int lane = t & 31;
    const int g    = lane >> 2;
    const int m2   = (lane & 3) * 2;
    const int bh   = blockIdx.y;
    const int q0   = blockIdx.x * QTILE;
    const int qrow = q0 + w * 16;

    const int kr = t >> 2, kc4 = t & 3;
    const int vr = t >> 3, vc8 = t & 7;
    const __half* gk = g_k + (size_t)bh * SP * HD;
    const __half* gv = g_vt + (size_t)bh * HD * SP + (size_t)vr * SP;
    uint32_t kdst[2], vdst[2];
    kdst[0] = smem_u32(&Kbuf[0][kr * STK + kc4 * 8]);
    kdst[1] = smem_u32(&Kbuf[1][kr * STK + kc4 * 8]);
    vdst[0] = smem_u32(&Vbuf[0][vr * STV + vc8 * 8]);
    vdst[1] = smem_u32(&Vbuf[1][vr * STV + vc8 * 8]);

    uint32_t kmat[2], vmat[2];
    {
        uint32_t ko = ((lane & 7) * STK + (lane >> 3) * 8) * 2;
        uint32_t vo = ((lane & 7) * STV + (lane >> 3) * 8) * 2;
        kmat[0] = smem_u32(Kbuf[0]) + ko; kmat[1] = smem_u32(Kbuf[1]) + ko;
        vmat[0] = smem_u32(Vbuf[0]) + vo; vmat[1] = smem_u32(Vbuf[1]) + vo;
    }

    uint32_t qa[2][4];
    {
        const __half* qb = g_q + (size_t)bh * SP * HD;
        int r0 = qrow + g, r1 = qrow + g + 8;
#pragma unroll
        for (int kc = 0; kc < 2; kc++) {
            int d0 = kc * 16 + m2, d1 = d0 + 8;
            qa[kc][0] = *(const uint32_t*)(qb + (size_t)r0 * HD + d0);
            qa[kc][1] = *(const uint32_t*)(qb + (size_t)r1 * HD + d0);
            qa[kc][2] = *(const uint32_t*)(qb + (size_t)r0 * HD + d1);
            qa[kc][3] = *(const uint32_t*)(qb + (size_t)r1 * HD + d1);
        }
    }

    float o[4][4];
#pragma unroll
    for (int i = 0; i < 4; i++)
#pragma unroll
        for (int j = 0; j < 4; j++) o[i][j] = 0.f;
    float la = 0.f, lb = 0.f;
    const uint32_t ONE2 = 0x3C003C00u;

    {
        CP16(kdst[0], gk + (size_t)kr * HD + kc4 * 8);
        CP16(vdst[0], gv + vc8 * 8);
        CPCOMMIT();
    }

    for (int kt = 0; kt < KT_TILES; kt++) {
        const int cur = kt & 1;
        __syncthreads();
        if (kt + 1 < KT_TILES) {
            int nk = kt + 1;
            CP16(cur ? kdst[0] : kdst[1], gk + (size_t)(nk * TKEY + kr) * HD + kc4 * 8);
            CP16(cur ? vdst[0] : vdst[1], gv + nk * TKEY + vc8 * 8);
        }
        CPCOMMIT();
        CPWAIT1();
        __syncthreads();

        uint32_t sh[8][2];
#pragma unroll
        for (int jn = 0; jn < 8; jn++) {
            uint32_t kb4[4];
            ldm4(kb4, kmat[cur] + jn * (8 * STK * 2));
            sh[jn][0] = 0u; sh[jn][1] = 0u;
            mma16816hh(sh[jn], qa[0], kb4 + 0, sh[jn]);
            mma16816hh(sh[jn], qa[1], kb4 + 2, sh[jn]);
        }

        uint32_t fh[8][2];
        if (kt < MASK_FROM) {
            uint32_t t01[8], t23[8];
#pragma unroll
            for (int jn = 0; jn < 8; jn++) {
                uint32_t p01 = ex2h2(sh[jn][0]);
                uint32_t p23 = ex2h2(sh[jn][1]);
                fh[jn][0] = hsub2u(p01, ONE2);
                fh[jn][1] = hsub2u(p23, ONE2);
                t01[jn] = p01; t23[jn] = p23;
            }
            uint32_t a0 = hadd2u(hadd2u(t01[0], t01[1]), hadd2u(t01[2], t01[3]));
            uint32_t a1 = hadd2u(hadd2u(t01[4], t01[5]), hadd2u(t01[6], t01[7]));
            uint32_t b0 = hadd2u(hadd2u(t23[0], t23[1]), hadd2u(t23[2], t23[3]));
            uint32_t b1 = hadd2u(hadd2u(t23[4], t23[5]), hadd2u(t23[6], t23[7]));
            a0 = hadd2u(a0, a1);
            b0 = hadd2u(b0, b1);
            __half2 ha = *(__half2*)&a0;
            __half2 hb = *(__half2*)&b0;
            la += __low2float(ha) + __high2float(ha);
            lb += __low2float(hb) + __high2float(hb);
        } else {
            const int kb = kt * TKEY;
#pragma unroll
            for (int jn = 0; jn < 8; jn++) {
                int col0 = kb + jn * 8 + m2;
                bool c0v = col0 < SS, c1v = (col0 + 1) < SS;
                float2 s01 = __half22float2(*(__half2*)&sh[jn][0]);
                float2 s23 = __half22float2(*(__half2*)&sh[jn][1]);
                float p0 = c0v ? ex2(s01.x) : 0.f;
                float p1 = c1v ? ex2(s01.y) : 0.f;
                float p2 = c0v ? ex2(s23.x) : 0.f;
                float p3 = c1v ? ex2(s23.y) : 0.f;
                la += p0 + p1;
                lb += p2 + p3;
                fh[jn][0] = packh(c0v ? (p0 - 1.f) : 0.f, c1v ? (p1 - 1.f) : 0.f);
                fh[jn][1] = packh(c0v ? (p2 - 1.f) : 0.f, c1v ? (p3 - 1.f) : 0.f);
            }
        }

        uint32_t pa[4][4];
#pragma unroll
        for (int kc2 = 0; kc2 < 4; kc2++) {
            pa[kc2][0] = fh[2 * kc2][0];
            pa[kc2][1] = fh[2 * kc2][1];
            pa[kc2][2] = fh[2 * kc2 + 1][0];
            pa[kc2][3] = fh[2 * kc2 + 1][1];
        }
#pragma unroll
        for (int jn2 = 0; jn2 < 4; jn2++) {
            uint32_t vv[8];
            ldm4(vv,     vmat[cur] + jn2 * (8 * STV * 2));
            ldm4(vv + 4, vmat[cur] + jn2 * (8 * STV * 2) + 64);
#pragma unroll
            for (int kc2 = 0; kc2 < 4; kc2++)
                mma16816h(o[jn2], pa[kc2], vv + 2 * kc2, o[jn2]);
        }
    }

    la += __shfl_xor_sync(0xffffffffu, la, 1);
    la += __shfl_xor_sync(0xffffffffu, la, 2);
    lb += __shfl_xor_sync(0xffffffffu, lb, 1);
    lb += __shfl_xor_sync(0xffffffffu, lb, 2);
    const float ia = 1.f / la, ib = 1.f / lb;

    const int b = bh >> 3;
    const int h = bh & 7;
    const int r0 = qrow + g, r1 = qrow + g + 8;
#pragma unroll
    for (int jn2 = 0; jn2 < 4; jn2++) {
        float2 vs = *(const float2*)&g_vsum[b * CC + h * HD + jn2 * 8 + m2];
        if (r0 < SS) {
            __half* dst = g_attnh + ((size_t)b * SS + r0) * CC + h * HD + jn2 * 8 + m2;
            *(__half2*)dst = __floats2half2_rn((o[jn2][0] + vs.x) * ia,
                                               (o[jn2][1] + vs.y) * ia);
        }
        if (r1 < SS) {
            __half* dst = g_attnh + ((size_t)b * SS + r1) * CC + h * HD + jn2 * 8 + m2;
            *(__half2*)dst = __floats2half2_rn((o[jn2][2] + vs.x) * ib,
                                               (o[jn2][3] + vs.y) * ib);
        }
    }
}

// ---------------------------------------------------------------------------
// LePE: 5x5 depthwise conv (SAME), sliding window, f16 RMW into g_attnh
// ---------------------------------------------------------------------------
#define XG 14
__global__ __launch_bounds__(256) void lepe_kernel(
    const float* __restrict__ x, const float* __restrict__ lw,
    const float* __restrict__ lb)
{
    __shared__ float wsh[25][256];
    const int c  = threadIdx.x;
    const int x0 = blockIdx.x * XG;
    const int y  = blockIdx.y;
    const int b  = blockIdx.z;

    for (int i = c; i < 25 * 256; i += 256)
        wsh[i % 25][i / 25] = lw[i];
    __syncthreads();
    float wt[25];
#pragma unroll
    for (int k = 0; k < 25; k++) wt[k] = wsh[k][c];
    const float lbv = lb[c];

    const float* xb = x + (size_t)b * HH * WW * CC + c;
    bool rv[5];
#pragma unroll
    for (int ky = 0; ky < 5; ky++) rv[ky] = (unsigned)(y + ky - 2) < (unsigned)HH;

    float win[5][5];
#pragma unroll
    for (int j = 0; j < 4; j++) {
        int col = x0 + j - 2;
        bool cv = (unsigned)col < (unsigned)WW;
#pragma unroll
        for (int ky = 0; ky < 5; ky++)
            win[j][ky] = (cv && rv[ky])
                ? xb[((size_t)(y + ky - 2) * WW + col) * CC] : 0.f;
    }

#pragma unroll
    for (int i = 0; i < XG; i++) {
        const int slot = (i + 4) % 5;
        int col = x0 + i + 2;
        bool cv = col < WW;
#pragma unroll
        for (int ky = 0; ky < 5; ky++)
            win[slot][ky] = (cv && rv[ky])
                ? xb[((size_t)(y + ky - 2) * WW + col) * CC] : 0.f;

        float sum = lbv;
#pragma unroll
        for (int kx = 0; kx < 5; kx++) {
            const int s = (i + kx) % 5;
#pragma unroll
            for (int ky = 0; ky < 5; ky++)
                sum += win[s][ky] * wt[ky * 5 + kx];
        }
        size_t idx = ((size_t)b * SS + 1 + y * WW + x0 + i) * CC + c;
        g_attnh[idx] = __float2half(__half2float(g_attnh[idx]) + sum);
    }
}

// ---------------------------------------------------------------------------
extern "C" void kernel_launch(void* const* d_in, const int* in_sizes, int n_in,
                              void* d_out, int out_size)
{
    const float* x      = (const float*)d_in[0];
    const float* cls    = (const float*)d_in[1];
    const float* qkv_w  = (const float*)d_in[2];
    const float* proj_w = (const float*)d_in[3];
    const float* proj_b = (const float*)d_in[4];
    const float* lepe_w = (const float*)d_in[5];
    const float* lepe_b = (const float*)d_in[6];

    float* out_x   = (float*)d_out;
    float* out_cls = (float*)d_out + in_sizes[0];

    // 0) column sums + fp16 conversion of x / weights
    vsum_a_kernel<<<256, 256>>>(x, qkv_w, proj_w);
    vsum_b_kernel<<<BB, 256>>>(cls, qkv_w);

    // 1) QKV projection: all-fp16 tensor-core GEMM
    hgemm_qkv_kernel<<<dim3((MROWS + 127) / 128, 768 / 128), 256>>>();

    // 2) fp16 mma.sync flash attention (f16-acc S GEMM) -> g_attnh
    attn_mma_kernel<<<dim3(SP / QTILE, BHN), 256>>>();

    // 3) LePE depthwise conv added into g_attnh (f16 RMW)
    lepe_kernel<<<dim3(WW / XG, HH, BB), 256>>>(x, lepe_w, lepe_b);

    // 4) Output projection: fp16 inputs, fp32 accumulate
    hgemm_proj_kernel<<<dim3((MROWS + 127) / 128, CC / 128), 256>>>(
        proj_b, out_x, out_cls);
}